// round 1
// baseline (speedup 1.0000x reference)
#include <cuda_runtime.h>

#define TT 128
#define DM 512
#define DFF 2048
#define NH 8
#define DH 64
#define NB 4
#define NL 4
#define THIST 120
#define NSTEPS 8
#define SCALE_EMB 22.627416997969522f
#define NEGF -3.4028234663852886e38f

// ---------------- scratch (static device memory; no allocs) ----------------
#define O_BUF   0         // [4][128][32]      16384
#define O_H     16384     // [4][128][512]     262144
#define O_Q     278528
#define O_K     540672
#define O_V     802816
#define O_ATTN  1064960
#define O_TMP   1327104
#define O_FF    1589248   // [4][128][2048]    1048576
#define O_CUR   2637824   // [4][32]           128
#define O_COMB  2637952   // [4][1024]         4096
#define O_HID   2642048   // [4][2048]         8192
#define SCRATCH_TOTAL 2650240

__device__ __align__(256) float g_scratch[SCRATCH_TOTAL];

__device__ __forceinline__ float gelu_f(float x) {
    float x3 = x * x * x;
    float t = tanhf(0.7978845608028654f * (x + 0.044715f * x3));
    return 0.5f * x * (1.0f + t);
}

// ---------------- init: fill buf with history, zero tail ----------------
__global__ void init_kernel(const float* __restrict__ history) {
    int idx = blockIdx.x * blockDim.x + threadIdx.x;  // < 4*128*32
    float* buf = g_scratch + O_BUF;
    int i = idx & 31;
    int t = (idx >> 5) & 127;
    int b = idx >> 12;
    buf[idx] = (t < THIST) ? history[(b * THIST + t) * 32 + i] : 0.0f;
}

// ---------------- generic tiled GEMM: Y[M,N] = X[M,K] @ W[N,K]^T ----------------
// epi: 0 = (+bias), 1 = (+bias, gelu), 2 = embed: ((+bias)*scale + pos_enc)
__device__ __forceinline__ void gemm_body(
    const float* __restrict__ X, const float* __restrict__ W,
    const float* __restrict__ bias, float* __restrict__ Y,
    int M, int N, int K, int epi)
{
    __shared__ __align__(16) float Xs[16][64];
    __shared__ __align__(16) float Ws[16][64];
    int tid = threadIdx.x;
    int tx = tid & 15, ty = tid >> 4;
    int bm = blockIdx.y * 64, bn = blockIdx.x * 64;
    int lrow = tid >> 2;
    int lk4 = (tid & 3) * 4;

    float acc[4][4];
#pragma unroll
    for (int i = 0; i < 4; i++)
#pragma unroll
        for (int j = 0; j < 4; j++) acc[i][j] = 0.0f;

    for (int k0 = 0; k0 < K; k0 += 16) {
        float4 xv = *(const float4*)(X + (size_t)(bm + lrow) * K + k0 + lk4);
        float4 wv = *(const float4*)(W + (size_t)(bn + lrow) * K + k0 + lk4);
        Xs[lk4 + 0][lrow] = xv.x; Xs[lk4 + 1][lrow] = xv.y;
        Xs[lk4 + 2][lrow] = xv.z; Xs[lk4 + 3][lrow] = xv.w;
        Ws[lk4 + 0][lrow] = wv.x; Ws[lk4 + 1][lrow] = wv.y;
        Ws[lk4 + 2][lrow] = wv.z; Ws[lk4 + 3][lrow] = wv.w;
        __syncthreads();
#pragma unroll
        for (int kk = 0; kk < 16; kk++) {
            float4 xr = *(const float4*)(&Xs[kk][ty * 4]);
            float4 wr = *(const float4*)(&Ws[kk][tx * 4]);
            acc[0][0] = fmaf(xr.x, wr.x, acc[0][0]);
            acc[0][1] = fmaf(xr.x, wr.y, acc[0][1]);
            acc[0][2] = fmaf(xr.x, wr.z, acc[0][2]);
            acc[0][3] = fmaf(xr.x, wr.w, acc[0][3]);
            acc[1][0] = fmaf(xr.y, wr.x, acc[1][0]);
            acc[1][1] = fmaf(xr.y, wr.y, acc[1][1]);
            acc[1][2] = fmaf(xr.y, wr.z, acc[1][2]);
            acc[1][3] = fmaf(xr.y, wr.w, acc[1][3]);
            acc[2][0] = fmaf(xr.z, wr.x, acc[2][0]);
            acc[2][1] = fmaf(xr.z, wr.y, acc[2][1]);
            acc[2][2] = fmaf(xr.z, wr.z, acc[2][2]);
            acc[2][3] = fmaf(xr.z, wr.w, acc[2][3]);
            acc[3][0] = fmaf(xr.w, wr.x, acc[3][0]);
            acc[3][1] = fmaf(xr.w, wr.y, acc[3][1]);
            acc[3][2] = fmaf(xr.w, wr.z, acc[3][2]);
            acc[3][3] = fmaf(xr.w, wr.w, acc[3][3]);
        }
        __syncthreads();
    }

#pragma unroll
    for (int i = 0; i < 4; i++) {
        int row = bm + ty * 4 + i;
#pragma unroll
        for (int j = 0; j < 4; j++) {
            int col = bn + tx * 4 + j;
            float v = acc[i][j];
            if (bias) v += bias[col];
            if (epi == 1) {
                v = gelu_f(v);
            } else if (epi == 2) {
                int t = row & 127;
                int i2 = col >> 1;
                float freq = expf(-0.017988946038835852f * (float)(2 * i2));
                float ang = (float)t * freq;
                float pe = (col & 1) ? cosf(ang) : sinf(ang);
                v = v * SCALE_EMB + pe;
            }
            Y[(size_t)row * N + col] = v;
        }
    }
}

__global__ void gemm_kernel(int xoff, const float* __restrict__ W,
                            const float* __restrict__ bias, int yoff,
                            int M, int N, int K, int epi) {
    gemm_body(g_scratch + xoff, W, bias, g_scratch + yoff, M, N, K, epi);
}

// fused QKV: blockIdx.z picks weight/output
__global__ void qkv_kernel(const float* __restrict__ Wq,
                           const float* __restrict__ Wk,
                           const float* __restrict__ Wv) {
    const float* W = (blockIdx.z == 0) ? Wq : (blockIdx.z == 1) ? Wk : Wv;
    int yoff = (blockIdx.z == 0) ? O_Q : (blockIdx.z == 1) ? O_K : O_V;
    gemm_body(g_scratch + O_H, W, nullptr, g_scratch + yoff, 512, 512, 512, 0);
}

// ---------------- attention: block per (qi, head, batch), 128 threads ----------------
__global__ void attn_kernel() {
    int qi = blockIdx.x, hh = blockIdx.y, b = blockIdx.z;
    int tid = threadIdx.x;  // 128
    const float* q = g_scratch + O_Q;
    const float* k = g_scratch + O_K;
    const float* v = g_scratch + O_V;
    float* out = g_scratch + O_ATTN;

    __shared__ float Ks[128][65];
    __shared__ float qrow[64];
    __shared__ float sw[128];
    __shared__ float red[128];

    const float* kbase = k + (size_t)b * TT * DM + hh * DH;
    for (int idx = tid * 4; idx < 128 * 64; idx += 128 * 4) {
        int kv = idx >> 6, d = idx & 63;
        float4 val = *(const float4*)(kbase + (size_t)kv * DM + d);
        Ks[kv][d] = val.x; Ks[kv][d + 1] = val.y;
        Ks[kv][d + 2] = val.z; Ks[kv][d + 3] = val.w;
    }
    if (tid < 64) qrow[tid] = q[((size_t)b * TT + qi) * DM + hh * DH + tid];
    __syncthreads();

    float acc = 0.0f;
#pragma unroll
    for (int d = 0; d < 64; d++) acc = fmaf(qrow[d], Ks[tid][d], acc);
    acc *= 0.125f;  // 1/sqrt(64)
    // faithful mask: attend only where kv > qi
    if (tid <= qi) acc = NEGF;

    red[tid] = acc;
    __syncthreads();
    for (int s = 64; s > 0; s >>= 1) {
        if (tid < s) red[tid] = fmaxf(red[tid], red[tid + s]);
        __syncthreads();
    }
    float m = red[0];
    __syncthreads();
    float e = expf(acc - m);
    sw[tid] = e;
    red[tid] = e;
    __syncthreads();
    for (int s = 64; s > 0; s >>= 1) {
        if (tid < s) red[tid] += red[tid + s];
        __syncthreads();
    }
    float inv = 1.0f / red[0];
    __syncthreads();

    if (tid < 64) {
        const float* vp = v + (size_t)b * TT * DM + hh * DH + tid;
        float o = 0.0f;
#pragma unroll 8
        for (int kv = 0; kv < 128; kv++) o = fmaf(sw[kv], vp[(size_t)kv * DM], o);
        out[((size_t)b * TT + qi) * DM + hh * DH + tid] = o * inv;
    }
}

// ---------------- residual + layernorm: h = LN(h + add) ----------------
__global__ void ln_kernel(int addoff, const float* __restrict__ g,
                          const float* __restrict__ bta) {
    int row = blockIdx.x;  // B*T
    int tid = threadIdx.x; // 256
    float* h = g_scratch + O_H;
    const float* add = g_scratch + addoff;
    size_t base = (size_t)row * DM;
    float x0 = h[base + tid] + add[base + tid];
    float x1 = h[base + tid + 256] + add[base + tid + 256];
    __shared__ float red[256];
    red[tid] = x0 + x1;
    __syncthreads();
    for (int s = 128; s > 0; s >>= 1) {
        if (tid < s) red[tid] += red[tid + s];
        __syncthreads();
    }
    float mu = red[0] * (1.0f / 512.0f);
    __syncthreads();
    float d0 = x0 - mu, d1 = x1 - mu;
    red[tid] = d0 * d0 + d1 * d1;
    __syncthreads();
    for (int s = 128; s > 0; s >>= 1) {
        if (tid < s) red[tid] += red[tid + s];
        __syncthreads();
    }
    float rstd = rsqrtf(red[0] * (1.0f / 512.0f) + 1e-5f);
    h[base + tid] = d0 * rstd * g[tid] + bta[tid];
    h[base + tid + 256] = d1 * rstd * g[tid + 256] + bta[tid + 256];
}

// ---------------- refine head ----------------
__global__ void refine_init_kernel(int step) {
    int b = blockIdx.x, tid = threadIdx.x;  // 512
    int ptr = THIST + step;
    float* cur = g_scratch + O_CUR;
    float* comb = g_scratch + O_COMB;
    const float* buf = g_scratch + O_BUF;
    const float* h = g_scratch + O_H;
    if (tid < 32) cur[b * 32 + tid] = buf[((size_t)b * TT + ptr - 1) * 32 + tid];
    comb[b * 1024 + 512 + tid] = h[((size_t)b * TT + ptr - 1) * DM + tid];
}

__global__ void refine_comb_kernel(const float* __restrict__ W_emb,
                                   const float* __restrict__ b_emb) {
    int b = blockIdx.x, tid = threadIdx.x;  // 512
    const float* cur = g_scratch + O_CUR;
    float* comb = g_scratch + O_COMB;
    __shared__ float c[32];
    if (tid < 32) c[tid] = cur[b * 32 + tid];
    __syncthreads();
    const float* w = W_emb + (size_t)tid * 32;
    float s = 0.0f;
#pragma unroll
    for (int i = 0; i < 32; i++) s = fmaf(w[i], c[i], s);
    comb[b * 1024 + tid] = (s + b_emb[tid]) * SCALE_EMB;
}

__global__ void refine_hidden_kernel(const float* __restrict__ Wr1,
                                     const float* __restrict__ br1) {
    int b = blockIdx.y;
    int tid = threadIdx.x;  // 256
    int w = tid >> 5, lane = tid & 31;
    const float* comb = g_scratch + O_COMB;
    float* hidden = g_scratch + O_HID;
    const float4* cb = (const float4*)(comb + b * 1024);
    float4 c[8];
#pragma unroll
    for (int jj = 0; jj < 8; jj++) c[jj] = cb[lane + 32 * jj];
    int obase = blockIdx.x * 128 + w * 16;
    for (int oo = 0; oo < 16; oo++) {
        int o = obase + oo;
        const float4* wr = (const float4*)(Wr1 + (size_t)o * 1024);
        float s = 0.0f;
#pragma unroll
        for (int jj = 0; jj < 8; jj++) {
            float4 wv = wr[lane + 32 * jj];
            s = fmaf(wv.x, c[jj].x, s);
            s = fmaf(wv.y, c[jj].y, s);
            s = fmaf(wv.z, c[jj].z, s);
            s = fmaf(wv.w, c[jj].w, s);
        }
#pragma unroll
        for (int off = 16; off; off >>= 1) s += __shfl_down_sync(0xffffffffu, s, off);
        if (lane == 0) hidden[b * 2048 + o] = gelu_f(s + br1[o]);
    }
}

__global__ void refine_delta_kernel(const float* __restrict__ Wr2,
                                    const float* __restrict__ br2,
                                    float* __restrict__ preds, int step, int last) {
    int b = blockIdx.x;
    int tid = threadIdx.x;  // 256
    int w = tid >> 5, lane = tid & 31;
    const float* hidden = g_scratch + O_HID;
    float* cur = g_scratch + O_CUR;
    float* buf = g_scratch + O_BUF;
    const float4* hv = (const float4*)(hidden + b * 2048);
    for (int oo = 0; oo < 4; oo++) {
        int o = w * 4 + oo;
        const float4* wr = (const float4*)(Wr2 + (size_t)o * 2048);
        float s = 0.0f;
#pragma unroll
        for (int jj = 0; jj < 16; jj++) {
            float4 wv = wr[lane + 32 * jj];
            float4 hx = hv[lane + 32 * jj];
            s = fmaf(wv.x, hx.x, s);
            s = fmaf(wv.y, hx.y, s);
            s = fmaf(wv.z, hx.z, s);
            s = fmaf(wv.w, hx.w, s);
        }
#pragma unroll
        for (int off = 16; off; off >>= 1) s += __shfl_down_sync(0xffffffffu, s, off);
        if (lane == 0) {
            float nv = cur[b * 32 + o] + s + br2[o];
            cur[b * 32 + o] = nv;
            if (last) {
                buf[((size_t)b * TT + THIST + step) * 32 + o] = nv;
                preds[(b * NSTEPS + step) * 32 + o] = nv;
            }
        }
    }
}

// ---------------- host orchestration ----------------
extern "C" void kernel_launch(void* const* d_in, const int* in_sizes, int n_in,
                              void* d_out, int out_size) {
    const float* history = (const float*)d_in[0];
    // d_in[1] = steps (constant 8, baked in)
    const float* W_emb = (const float*)d_in[2];
    const float* b_emb = (const float*)d_in[3];
    const float* Wq = (const float*)d_in[4];
    const float* Wk = (const float*)d_in[5];
    const float* Wv = (const float*)d_in[6];
    const float* Wo = (const float*)d_in[7];
    const float* ln1g = (const float*)d_in[8];
    const float* ln1b = (const float*)d_in[9];
    const float* W1 = (const float*)d_in[10];
    const float* b1 = (const float*)d_in[11];
    const float* W2 = (const float*)d_in[12];
    const float* b2 = (const float*)d_in[13];
    const float* ln2g = (const float*)d_in[14];
    const float* ln2b = (const float*)d_in[15];
    const float* Wr1 = (const float*)d_in[16];
    const float* br1 = (const float*)d_in[17];
    const float* Wr2 = (const float*)d_in[18];
    const float* br2 = (const float*)d_in[19];
    float* preds = (float*)d_out;

    init_kernel<<<64, 256>>>(history);

    for (int step = 0; step < NSTEPS; step++) {
        // embed: h = (buf @ W_emb^T + b_emb)*scale + pe   (M=512,N=512,K=32)
        gemm_kernel<<<dim3(8, 8), 256>>>(O_BUF, W_emb, b_emb, O_H, 512, 512, 32, 2);

        for (int l = 0; l < NL; l++) {
            qkv_kernel<<<dim3(8, 8, 3), 256>>>(Wq + (size_t)l * 262144,
                                               Wk + (size_t)l * 262144,
                                               Wv + (size_t)l * 262144);
            attn_kernel<<<dim3(128, 8, 4), 128>>>();
            gemm_kernel<<<dim3(8, 8), 256>>>(O_ATTN, Wo + (size_t)l * 262144,
                                             nullptr, O_TMP, 512, 512, 512, 0);
            ln_kernel<<<512, 256>>>(O_TMP, ln1g + l * 512, ln1b + l * 512);
            gemm_kernel<<<dim3(32, 8), 256>>>(O_H, W1 + (size_t)l * 1048576,
                                              b1 + l * 2048, O_FF, 512, 2048, 512, 1);
            gemm_kernel<<<dim3(8, 8), 256>>>(O_FF, W2 + (size_t)l * 1048576,
                                             b2 + l * 512, O_TMP, 512, 512, 2048, 0);
            ln_kernel<<<512, 256>>>(O_TMP, ln2g + l * 512, ln2b + l * 512);
        }

        refine_init_kernel<<<4, 512>>>(step);
        for (int it = 0; it < 5; it++) {
            refine_comb_kernel<<<4, 512>>>(W_emb, b_emb);
            refine_hidden_kernel<<<dim3(16, 4), 256>>>(Wr1, br1);
            refine_delta_kernel<<<4, 256>>>(Wr2, br2, preds, step, it == 4);
        }
    }
}

// round 5
// speedup vs baseline: 1.1998x; 1.1998x over previous
#include <cuda_runtime.h>
#include <cuda_bf16.h>
#include <cstdint>

#define TT 128
#define DM 512
#define DFF 2048
#define NH 8
#define DH 64
#define NB 4
#define NL 4
#define THIST 120
#define NSTEPS 8
#define SCALE_EMB 22.627416997969522f
#define NEGF -3.4028234663852886e38f

// ---------------- fp32 scratch ----------------
#define O_BUF   0         // [4][128][32]
#define O_H     16384     // [4][128][512]
#define O_Q     278528
#define O_K     540672
#define O_V     802816
#define O_TMP   1327104
#define O_CUR   2637824   // [4][32]
#define O_CTX   2637952   // [4][512]
#define O_HID   2646144   // [4][2048]
#define SCRATCH_TOTAL 2654336
__device__ __align__(256) float g_scratch[SCRATCH_TOTAL];

// ---------------- bf16 scratch (hi/lo split) ----------------
#define BF_WQKVO_H 0
#define BF_WQKVO_L 4194304
#define BF_W1H     8388608
#define BF_W1L     12582912
#define BF_W2H     16777216
#define BF_W2L     20971520
#define BF_HH      25165824
#define BF_HL      25427968
#define BF_AH      25690112
#define BF_AL      25952256
#define BF_FFH     26214400
#define BF_FFL     27262976
#define BF_TOTAL   28311552
__device__ __align__(256) __nv_bfloat16 g_bf[BF_TOTAL];

__device__ __forceinline__ float gelu_f(float x) {
    float x3 = x * x * x;
    float t = tanhf(0.7978845608028654f * (x + 0.044715f * x3));
    return 0.5f * x * (1.0f + t);
}

__device__ __forceinline__ uint32_t smem_u32(const void* p) {
    uint32_t a;
    asm("{ .reg .u64 t; cvta.to.shared.u64 t, %1; cvt.u32.u64 %0, t; }" : "=r"(a) : "l"(p));
    return a;
}
__device__ __forceinline__ void ldmx4(uint32_t* r, uint32_t addr) {
    asm volatile("ldmatrix.sync.aligned.m8n8.x4.shared.b16 {%0,%1,%2,%3}, [%4];"
                 : "=r"(r[0]), "=r"(r[1]), "=r"(r[2]), "=r"(r[3]) : "r"(addr));
}
__device__ __forceinline__ void mma16816(float* c, const uint32_t* a,
                                         uint32_t b0, uint32_t b1) {
    asm volatile(
        "mma.sync.aligned.m16n8k16.row.col.f32.bf16.bf16.f32 "
        "{%0,%1,%2,%3}, {%4,%5,%6,%7}, {%8,%9}, {%0,%1,%2,%3};"
        : "+f"(c[0]), "+f"(c[1]), "+f"(c[2]), "+f"(c[3])
        : "r"(a[0]), "r"(a[1]), "r"(a[2]), "r"(a[3]), "r"(b0), "r"(b1));
}

// ---------------- init ----------------
__global__ void init_kernel(const float* __restrict__ history) {
    int idx = blockIdx.x * blockDim.x + threadIdx.x;
    float* buf = g_scratch + O_BUF;
    int i = idx & 31;
    int t = (idx >> 5) & 127;
    int b = idx >> 12;
    buf[idx] = (t < THIST) ? history[(b * THIST + t) * 32 + i] : 0.0f;
}

// ---------------- weight hi/lo conversion ----------------
__global__ void convert_kernel(const float* __restrict__ src, int hi_off, int lo_off, int n) {
    for (int i = blockIdx.x * blockDim.x + threadIdx.x; i < n; i += gridDim.x * blockDim.x) {
        float v = src[i];
        __nv_bfloat16 h = __float2bfloat16(v);
        g_bf[hi_off + i] = h;
        g_bf[lo_off + i] = __float2bfloat16(v - __bfloat162float(h));
    }
}

// ---------------- HMMA GEMM: Y[128-tile, 64-tile] = A[M,K] @ W[N,K]^T ----------------
// 3-pass hi/lo: Ahi*Whi + Alo*Whi + Ahi*Wlo, fp32 accum.
// mode 0: fp32 out; mode 1: +bias,gelu -> bf16 hi/lo; mode 2: +bias fp32 out.
#define ASTR 40   // padded bf16 row stride (80B: ldmatrix conflict-free)
__global__ __launch_bounds__(256, 2) void mma_gemm_kernel(
    int aHiOff, int aLoOff, int wHiOff, int wLoOff, int wZs,
    const float* __restrict__ bias, int ofOff, int oZs,
    int ohOff, int olOff, int N, int K, int mode)
{
    __shared__ __align__(16) __nv_bfloat16 As[2][128 * ASTR];
    __shared__ __align__(16) __nv_bfloat16 Bs[2][64 * ASTR];

    const int tid = threadIdx.x;
    const int warp = tid >> 5, lane = tid & 31;
    const int wm = (warp & 3) * 32;       // warp row offset in 128
    const int wn = (warp >> 2) * 32;      // warp col offset in 64
    const int bn = blockIdx.x * 64;
    const int bm = blockIdx.y * 128;
    const int z = blockIdx.z;

    const __nv_bfloat16* Ahi = g_bf + aHiOff;
    const __nv_bfloat16* Alo = g_bf + aLoOff;
    const __nv_bfloat16* Whi = g_bf + wHiOff + (size_t)z * wZs;
    const __nv_bfloat16* Wlo = g_bf + wLoOff + (size_t)z * wZs;

    const int kc = K >> 5;        // 32-wide chunks per pass
    const int C = 3 * kc;

    // global load indices
    const int ar0 = tid >> 2;           // A rows: ar0, ar0+64
    const int aq = (tid & 3) * 8;
    const int br0 = tid >> 2;           // B row (0..63)

    float acc[2][4][4];
#pragma unroll
    for (int mt = 0; mt < 2; mt++)
#pragma unroll
        for (int nt = 0; nt < 4; nt++)
#pragma unroll
            for (int i = 0; i < 4; i++) acc[mt][nt][i] = 0.0f;

    uint4 pA0, pA1, pB;
    {   // chunk 0 (pass 0)
        pA0 = *(const uint4*)(Ahi + (size_t)(bm + ar0) * K + aq);
        pA1 = *(const uint4*)(Ahi + (size_t)(bm + ar0 + 64) * K + aq);
        pB  = *(const uint4*)(Whi + (size_t)(bn + br0) * K + aq);
    }
    *(uint4*)(&As[0][ar0 * ASTR + aq]) = pA0;
    *(uint4*)(&As[0][(ar0 + 64) * ASTR + aq]) = pA1;
    *(uint4*)(&Bs[0][br0 * ASTR + aq]) = pB;
    __syncthreads();

    for (int c = 0; c < C; c++) {
        if (c + 1 < C) {
            int cn = c + 1;
            int pass = cn / kc;
            int k0 = (cn - pass * kc) << 5;
            const __nv_bfloat16* Ag = (pass == 1) ? Alo : Ahi;
            const __nv_bfloat16* Wg = (pass == 2) ? Wlo : Whi;
            pA0 = *(const uint4*)(Ag + (size_t)(bm + ar0) * K + k0 + aq);
            pA1 = *(const uint4*)(Ag + (size_t)(bm + ar0 + 64) * K + k0 + aq);
            pB  = *(const uint4*)(Wg + (size_t)(bn + br0) * K + k0 + aq);
        }

        // compute chunk c from smem buffer c&1
        uint32_t sA = smem_u32(&As[c & 1][0]);
        uint32_t sB = smem_u32(&Bs[c & 1][0]);
#pragma unroll
        for (int ks = 0; ks < 2; ks++) {
            int k16 = ks * 16;
            uint32_t af[2][4];
            uint32_t abase = sA + 80u * (wm + (lane & 15)) + 2u * (k16 + ((lane >> 4) << 3));
            ldmx4(af[0], abase);
            ldmx4(af[1], abase + 16 * 80);
            uint32_t q0[4], q1[4];
            uint32_t bbase = sB + 80u * (wn + (lane & 7) + ((lane >> 4) << 3))
                                + 2u * (k16 + (((lane >> 3) & 1) << 3));
            ldmx4(q0, bbase);
            ldmx4(q1, bbase + 16 * 80);
#pragma unroll
            for (int mt = 0; mt < 2; mt++) {
                mma16816(acc[mt][0], af[mt], q0[0], q0[1]);
                mma16816(acc[mt][1], af[mt], q0[2], q0[3]);
                mma16816(acc[mt][2], af[mt], q1[0], q1[1]);
                mma16816(acc[mt][3], af[mt], q1[2], q1[3]);
            }
        }

        if (c + 1 < C) {
            int s = (c + 1) & 1;
            *(uint4*)(&As[s][ar0 * ASTR + aq]) = pA0;
            *(uint4*)(&As[s][(ar0 + 64) * ASTR + aq]) = pA1;
            *(uint4*)(&Bs[s][br0 * ASTR + aq]) = pB;
            __syncthreads();
        }
    }

    // epilogue
    const int l4 = lane >> 2;
    const int l2 = (lane & 3) * 2;
    if (mode == 1) {
        __nv_bfloat16* oh = g_bf + ohOff;
        __nv_bfloat16* ol = g_bf + olOff;
#pragma unroll
        for (int mt = 0; mt < 2; mt++)
#pragma unroll
            for (int i2 = 0; i2 < 2; i2++) {
                int m = bm + wm + mt * 16 + l4 + i2 * 8;
                size_t rowb = (size_t)m * N;
#pragma unroll
                for (int nt = 0; nt < 4; nt++) {
                    int n = bn + wn + nt * 8 + l2;
                    float v0 = gelu_f(acc[mt][nt][i2 * 2 + 0] + bias[n]);
                    float v1 = gelu_f(acc[mt][nt][i2 * 2 + 1] + bias[n + 1]);
                    __nv_bfloat16 h0 = __float2bfloat16(v0);
                    __nv_bfloat16 h1 = __float2bfloat16(v1);
                    __nv_bfloat162 hv; hv.x = h0; hv.y = h1;
                    *(__nv_bfloat162*)(oh + rowb + n) = hv;
                    __nv_bfloat162 lv;
                    lv.x = __float2bfloat16(v0 - __bfloat162float(h0));
                    lv.y = __float2bfloat16(v1 - __bfloat162float(h1));
                    *(__nv_bfloat162*)(ol + rowb + n) = lv;
                }
            }
    } else {
        float* of = g_scratch + ofOff + (size_t)z * oZs;
#pragma unroll
        for (int mt = 0; mt < 2; mt++)
#pragma unroll
            for (int i2 = 0; i2 < 2; i2++) {
                int m = bm + wm + mt * 16 + l4 + i2 * 8;
                size_t rowb = (size_t)m * N;
#pragma unroll
                for (int nt = 0; nt < 4; nt++) {
                    int n = bn + wn + nt * 8 + l2;
                    float v0 = acc[mt][nt][i2 * 2 + 0];
                    float v1 = acc[mt][nt][i2 * 2 + 1];
                    if (mode == 2) { v0 += bias[n]; v1 += bias[n + 1]; }
                    float2 fv; fv.x = v0; fv.y = v1;
                    *(float2*)(of + rowb + n) = fv;
                }
            }
    }
}

// ---------------- embed (fp32 SIMT, K=32) ----------------
__global__ void embed_kernel(const float* __restrict__ W, const float* __restrict__ bias) {
    __shared__ __align__(16) float Xs[16][32];
    __shared__ __align__(16) float Ws[16][64];
    const float* X = g_scratch + O_BUF;
    float* Y = g_scratch + O_H;
    int tid = threadIdx.x;
    int tx = tid & 15, ty = tid >> 4;
    int bm = blockIdx.y * 32, bn = blockIdx.x * 64;
    int lrow = tid >> 2;
    int lk4 = (tid & 3) * 4;
    const int K = 32;

    float acc[2][4];
#pragma unroll
    for (int i = 0; i < 2; i++)
#pragma unroll
        for (int j = 0; j < 4; j++) acc[i][j] = 0.0f;

    for (int k0 = 0; k0 < K; k0 += 16) {
        float4 wv = *(const float4*)(W + (size_t)(bn + lrow) * K + k0 + lk4);
        Ws[lk4 + 0][lrow] = wv.x; Ws[lk4 + 1][lrow] = wv.y;
        Ws[lk4 + 2][lrow] = wv.z; Ws[lk4 + 3][lrow] = wv.w;
        if (tid < 128) {
            float4 xv = *(const float4*)(X + (size_t)(bm + (lrow & 31)) * K + k0 + lk4);
            Xs[lk4 + 0][lrow] = xv.x; Xs[lk4 + 1][lrow] = xv.y;
            Xs[lk4 + 2][lrow] = xv.z; Xs[lk4 + 3][lrow] = xv.w;
        }
        __syncthreads();
#pragma unroll
        for (int kk = 0; kk < 16; kk++) {
            float2 xr = *(const float2*)(&Xs[kk][ty * 2]);
            float4 wr = *(const float4*)(&Ws[kk][tx * 4]);
            acc[0][0] = fmaf(xr.x, wr.x, acc[0][0]);
            acc[0][1] = fmaf(xr.x, wr.y, acc[0][1]);
            acc[0][2] = fmaf(xr.x, wr.z, acc[0][2]);
            acc[0][3] = fmaf(xr.x, wr.w, acc[0][3]);
            acc[1][0] = fmaf(xr.y, wr.x, acc[1][0]);
            acc[1][1] = fmaf(xr.y, wr.y, acc[1][1]);
            acc[1][2] = fmaf(xr.y, wr.z, acc[1][2]);
            acc[1][3] = fmaf(xr.y, wr.w, acc[1][3]);
        }
        __syncthreads();
    }

#pragma unroll
    for (int i = 0; i < 2; i++) {
        int row = bm + ty * 2 + i;
#pragma unroll
        for (int j = 0; j < 4; j++) {
            int col = bn + tx * 4 + j;
            float v = acc[i][j] + bias[col];
            int t = row & 127;
            int i2 = col >> 1;
            float freq = expf(-0.017988946038835852f * (float)(2 * i2));
            float ang = (float)t * freq;
            float pe = (col & 1) ? cosf(ang) : sinf(ang);
            v = v * SCALE_EMB + pe;
            Y[(size_t)row * DM + col] = v;
            __nv_bfloat16 h = __float2bfloat16(v);
            g_bf[BF_HH + row * DM + col] = h;
            g_bf[BF_HL + row * DM + col] = __float2bfloat16(v - __bfloat162float(h));
        }
    }
}

// ---------------- attention ----------------
__global__ void attn_kernel() {
    int qc = blockIdx.x, hh = blockIdx.y, b = blockIdx.z;
    int tid = threadIdx.x;
    int warp = tid >> 5, lane = tid & 31;

    __shared__ float Ks[64][132];
    __shared__ float Qs[32][64];
    __shared__ float Wb[8][128];

    const float* q = g_scratch + O_Q;
    const float* k = g_scratch + O_K;
    const float* v = g_scratch + O_V;

    const float* kbase = k + (size_t)b * TT * DM + hh * DH;
    for (int idx = tid; idx < 128 * 16; idx += 256) {
        int kv = idx & 127, d4 = (idx >> 7) * 4;
        float4 val = *(const float4*)(kbase + (size_t)kv * DM + d4);
        Ks[d4 + 0][kv] = val.x; Ks[d4 + 1][kv] = val.y;
        Ks[d4 + 2][kv] = val.z; Ks[d4 + 3][kv] = val.w;
    }
    const float* qbase = q + ((size_t)b * TT + qc * 32) * DM + hh * DH;
    for (int idx = tid; idx < 32 * 16; idx += 256) {
        int qi = idx >> 4, d4 = (idx & 15) * 4;
        *(float4*)(&Qs[qi][d4]) = *(const float4*)(qbase + (size_t)qi * DM + d4);
    }
    __syncthreads();

    const float* vbase = v + (size_t)b * TT * DM + hh * DH;

#pragma unroll
    for (int qq = 0; qq < 4; qq++) {
        int qi = warp + qq * 8;
        int qg = qc * 32 + qi;

        float acc0 = 0.f, acc1 = 0.f, acc2 = 0.f, acc3 = 0.f;
#pragma unroll 8
        for (int d = 0; d < 64; d++) {
            float qv = Qs[qi][d];
            float4 kvv = *(const float4*)(&Ks[d][4 * lane]);
            acc0 = fmaf(qv, kvv.x, acc0);
            acc1 = fmaf(qv, kvv.y, acc1);
            acc2 = fmaf(qv, kvv.z, acc2);
            acc3 = fmaf(qv, kvv.w, acc3);
        }
        int kv0 = 4 * lane;
        acc0 = (kv0 + 0 <= qg) ? NEGF : acc0 * 0.125f;
        acc1 = (kv0 + 1 <= qg) ? NEGF : acc1 * 0.125f;
        acc2 = (kv0 + 2 <= qg) ? NEGF : acc2 * 0.125f;
        acc3 = (kv0 + 3 <= qg) ? NEGF : acc3 * 0.125f;

        float m = fmaxf(fmaxf(acc0, acc1), fmaxf(acc2, acc3));
#pragma unroll
        for (int off = 16; off; off >>= 1)
            m = fmaxf(m, __shfl_xor_sync(0xffffffffu, m, off));
        float e0 = expf(acc0 - m), e1 = expf(acc1 - m);
        float e2 = expf(acc2 - m), e3 = expf(acc3 - m);
        float s = e0 + e1 + e2 + e3;
#pragma unroll
        for (int off = 16; off; off >>= 1)
            s += __shfl_xor_sync(0xffffffffu, s, off);
        float inv = 1.0f / s;

        Wb[warp][kv0 + 0] = e0; Wb[warp][kv0 + 1] = e1;
        Wb[warp][kv0 + 2] = e2; Wb[warp][kv0 + 3] = e3;
        __syncwarp();

        float2 o = make_float2(0.f, 0.f);
        const float* vp = vbase + 2 * lane;
#pragma unroll 4
        for (int kv = 0; kv < 128; kv++) {
            float w = Wb[warp][kv];
            float2 vv = *(const float2*)(vp + (size_t)kv * DM);
            o.x = fmaf(w, vv.x, o.x);
            o.y = fmaf(w, vv.y, o.y);
        }
        o.x *= inv; o.y *= inv;
        int oidx = ((b * TT + qg) * DM) + hh * DH + 2 * lane;
        __nv_bfloat16 hx = __float2bfloat16(o.x);
        __nv_bfloat16 hy = __float2bfloat16(o.y);
        g_bf[BF_AH + oidx + 0] = hx;
        g_bf[BF_AH + oidx + 1] = hy;
        g_bf[BF_AL + oidx + 0] = __float2bfloat16(o.x - __bfloat162float(hx));
        g_bf[BF_AL + oidx + 1] = __float2bfloat16(o.y - __bfloat162float(hy));
        __syncwarp();
    }
}

// ---------------- residual + layernorm (+ hi/lo emit) ----------------
__global__ void ln_kernel(int addoff, const float* __restrict__ g,
                          const float* __restrict__ bta) {
    int row = blockIdx.x;
    int tid = threadIdx.x;
    float* h = g_scratch + O_H;
    const float* add = g_scratch + addoff;
    size_t base = (size_t)row * DM;
    float x0 = h[base + tid] + add[base + tid];
    float x1 = h[base + tid + 256] + add[base + tid + 256];
    __shared__ float red[256];
    red[tid] = x0 + x1;
    __syncthreads();
    for (int s = 128; s > 0; s >>= 1) {
        if (tid < s) red[tid] += red[tid + s];
        __syncthreads();
    }
    float mu = red[0] * (1.0f / 512.0f);
    __syncthreads();
    float d0 = x0 - mu, d1 = x1 - mu;
    red[tid] = d0 * d0 + d1 * d1;
    __syncthreads();
    for (int s = 128; s > 0; s >>= 1) {
        if (tid < s) red[tid] += red[tid + s];
        __syncthreads();
    }
    float rstd = rsqrtf(red[0] * (1.0f / 512.0f) + 1e-5f);
    float y0 = d0 * rstd * g[tid] + bta[tid];
    float y1 = d1 * rstd * g[tid + 256] + bta[tid + 256];
    h[base + tid] = y0;
    h[base + tid + 256] = y1;
    __nv_bfloat16 h0 = __float2bfloat16(y0);
    __nv_bfloat16 h1 = __float2bfloat16(y1);
    g_bf[BF_HH + base + tid] = h0;
    g_bf[BF_HH + base + tid + 256] = h1;
    g_bf[BF_HL + base + tid] = __float2bfloat16(y0 - __bfloat162float(h0));
    g_bf[BF_HL + base + tid + 256] = __float2bfloat16(y1 - __bfloat162float(h1));
}

// ---------------- refine head ----------------
__global__ void refine_init_kernel(int step) {
    int b = blockIdx.x, tid = threadIdx.x;
    int ptr = THIST + step;
    float* cur = g_scratch + O_CUR;
    float* ctx = g_scratch + O_CTX;
    const float* buf = g_scratch + O_BUF;
    const float* h = g_scratch + O_H;
    if (tid < 32) cur[b * 32 + tid] = buf[((size_t)b * TT + ptr - 1) * 32 + tid];
    ctx[b * 512 + tid] = h[((size_t)b * TT + ptr - 1) * DM + tid];
}

__global__ void refine_hidden_kernel(const float* __restrict__ Wr1,
                                     const float* __restrict__ br1,
                                     const float* __restrict__ W_emb,
                                     const float* __restrict__ b_emb) {
    int b = blockIdx.y;
    int tid = threadIdx.x;
    int w = tid >> 5, lane = tid & 31;
    float* hidden = g_scratch + O_HID;
    const float* ctx = g_scratch + O_CTX;
    const float* cur = g_scratch + O_CUR;

    __shared__ __align__(16) float comb[1024];
    __shared__ float curs[32];
    if (tid < 32) curs[tid] = cur[b * 32 + tid];
    __syncthreads();
    for (int r = tid; r < 512; r += 256) {
        const float* we = W_emb + (size_t)r * 32;
        float s = 0.0f;
#pragma unroll
        for (int i = 0; i < 32; i++) s = fmaf(we[i], curs[i], s);
        comb[r] = (s + b_emb[r]) * SCALE_EMB;
        comb[512 + r] = ctx[b * 512 + r];
    }
    __syncthreads();

    const float4* cb = (const float4*)comb;
    float4 c[8];
#pragma unroll
    for (int jj = 0; jj < 8; jj++) c[jj] = cb[lane + 32 * jj];
    int obase = blockIdx.x * 128 + w * 16;
    for (int oo = 0; oo < 16; oo++) {
        int o = obase + oo;
        const float4* wr = (const float4*)(Wr1 + (size_t)o * 1024);
        float s = 0.0f;
#pragma unroll
        for (int jj = 0; jj < 8; jj++) {
            float4 wv = wr[lane + 32 * jj];
            s = fmaf(wv.x, c[jj].x, s);
            s = fmaf(wv.y, c[jj].y, s);
            s = fmaf(wv.z, c[jj].z, s);
            s = fmaf(wv.w, c[jj].w, s);
        }
#pragma unroll
        for (int off = 16; off; off >>= 1) s += __shfl_down_sync(0xffffffffu, s, off);
        if (lane == 0) hidden[b * 2048 + o] = gelu_f(s + br1[o]);
    }
}

__global__ void refine_delta_kernel(const float* __restrict__ Wr2,
                                    const float* __restrict__ br2,
                                    float* __restrict__ preds, int step, int last) {
    int b = blockIdx.x;
    int tid = threadIdx.x;
    int w = tid >> 5, lane = tid & 31;
    const float* hidden = g_scratch + O_HID;
    float* cur = g_scratch + O_CUR;
    float* buf = g_scratch + O_BUF;
    const float4* hv = (const float4*)(hidden + b * 2048);
    for (int oo = 0; oo < 4; oo++) {
        int o = w * 4 + oo;
        const float4* wr = (const float4*)(Wr2 + (size_t)o * 2048);
        float s = 0.0f;
#pragma unroll
        for (int jj = 0; jj < 16; jj++) {
            float4 wv = wr[lane + 32 * jj];
            float4 hx = hv[lane + 32 * jj];
            s = fmaf(wv.x, hx.x, s);
            s = fmaf(wv.y, hx.y, s);
            s = fmaf(wv.z, hx.z, s);
            s = fmaf(wv.w, hx.w, s);
        }
#pragma unroll
        for (int off = 16; off; off >>= 1) s += __shfl_down_sync(0xffffffffu, s, off);
        if (lane == 0) {
            float nv = cur[b * 32 + o] + s + br2[o];
            cur[b * 32 + o] = nv;
            if (last) {
                buf[((size_t)b * TT + THIST + step) * 32 + o] = nv;
                preds[(b * NSTEPS + step) * 32 + o] = nv;
            }
        }
    }
}

// ---------------- host orchestration ----------------
extern "C" void kernel_launch(void* const* d_in, const int* in_sizes, int n_in,
                              void* d_out, int out_size) {
    const float* history = (const float*)d_in[0];
    const float* W_emb = (const float*)d_in[2];
    const float* b_emb = (const float*)d_in[3];
    const float* Wq = (const float*)d_in[4];
    const float* Wk = (const float*)d_in[5];
    const float* Wv = (const float*)d_in[6];
    const float* Wo = (const float*)d_in[7];
    const float* ln1g = (const float*)d_in[8];
    const float* ln1b = (const float*)d_in[9];
    const float* W1 = (const float*)d_in[10];
    const float* b1 = (const float*)d_in[11];
    const float* W2 = (const float*)d_in[12];
    const float* b2 = (const float*)d_in[13];
    const float* ln2g = (const float*)d_in[14];
    const float* ln2b = (const float*)d_in[15];
    const float* Wr1 = (const float*)d_in[16];
    const float* br1 = (const float*)d_in[17];
    const float* Wr2 = (const float*)d_in[18];
    const float* br2 = (const float*)d_in[19];
    float* preds = (float*)d_out;

    // weight hi/lo conversion (once per launch)
    convert_kernel<<<2048, 256>>>(Wq, BF_WQKVO_H + 0 * 1048576, BF_WQKVO_L + 0 * 1048576, 1048576);
    convert_kernel<<<2048, 256>>>(Wk, BF_WQKVO_H + 1 * 1048576, BF_WQKVO_L + 1 * 1048576, 1048576);
    convert_kernel<<<2048, 256>>>(Wv, BF_WQKVO_H + 2 * 1048576, BF_WQKVO_L + 2 * 1048576, 1048576);
    convert_kernel<<<2048, 256>>>(Wo, BF_WQKVO_H + 3 * 1048576, BF_WQKVO_L + 3 * 1048576, 1048576);
    convert_kernel<<<4096, 256>>>(W1, BF_W1H, BF_W1L, 4194304);
    convert_kernel<<<4096, 256>>>(W2, BF_W2H, BF_W2L, 4194304);

    init_kernel<<<64, 256>>>(history);

    for (int step = 0; step < NSTEPS; step++) {
        embed_kernel<<<dim3(8, 16), 256>>>(W_emb, b_emb);

        for (int l = 0; l < NL; l++) {
            // QKV fused over z (mode 0)
            mma_gemm_kernel<<<dim3(8, 4, 3), 256>>>(
                BF_HH, BF_HL,
                BF_WQKVO_H + l * 262144, BF_WQKVO_L + l * 262144, 1048576,
                nullptr, O_Q, 262144, 0, 0, 512, 512, 0);
            attn_kernel<<<dim3(4, 8, 4), 256>>>();
            // O projection
            mma_gemm_kernel<<<dim3(8, 4, 1), 256>>>(
                BF_AH, BF_AL,
                BF_WQKVO_H + 3145728 + l * 262144, BF_WQKVO_L + 3145728 + l * 262144, 0,
                nullptr, O_TMP, 0, 0, 0, 512, 512, 0);
            ln_kernel<<<512, 256>>>(O_TMP, ln1g + l * 512, ln1b + l * 512);
            // FF1 (bias+gelu -> bf16 hi/lo)
            mma_gemm_kernel<<<dim3(32, 4, 1), 256>>>(
                BF_HH, BF_HL,
                BF_W1H + l * 1048576, BF_W1L + l * 1048576, 0,
                b1 + l * 2048, 0, 0, BF_FFH, BF_FFL, 2048, 512, 1);
            // FF2 (+bias fp32)
            mma_gemm_kernel<<<dim3(8, 4, 1), 256>>>(
                BF_FFH, BF_FFL,
                BF_W2H + l * 1048576, BF_W2L + l * 1048576, 0,
                b2 + l * 512, O_TMP, 0, 0, 0, 512, 2048, 2);
            ln_kernel<<<512, 256>>>(O_TMP, ln2g + l * 512, ln2b + l * 512);
        }

        refine_init_kernel<<<4, 512>>>(step);
        for (int it = 0; it < 5; it++) {
            refine_hidden_kernel<<<dim3(16, 4), 256>>>(Wr1, br1, W_emb, b_emb);
            refine_delta_kernel<<<4, 256>>>(Wr2, br2, preds, step, it == 4);
        }
    }
}

// round 6
// speedup vs baseline: 1.8027x; 1.5026x over previous
#include <cuda_runtime.h>
#include <cstdint>

#define TT 128
#define DM 512
#define DFF 2048
#define NH 8
#define DH 64
#define NB 4
#define NL 4
#define THIST 120
#define NSTEPS 8
#define SCALE_EMB 22.627416997969522f
#define NEGF -3.4028234663852886e38f

// ---------------- fp32 scratch ----------------
#define O_BUF   0         // [4][128][32]
#define O_H     16384     // [4][128][512]
#define O_Q     278528
#define O_K     540672
#define O_V     802816
#define O_ATTN  1064960
#define O_TMP   1327104
#define O_FF    1589248   // [4][128][2048]
#define O_CUR   2637824   // [4][32]
#define O_CTX   2637952   // [4][512]
#define O_HID   2646144   // [4][2048]
#define SCRATCH_TOTAL 2654336
__device__ __align__(256) float g_scratch[SCRATCH_TOTAL];

__device__ __forceinline__ float gelu_f(float x) {
    float x3 = x * x * x;
    float t = tanhf(0.7978845608028654f * (x + 0.044715f * x3));
    return 0.5f * x * (1.0f + t);
}

__device__ __forceinline__ uint32_t smem_u32(const void* p) {
    uint32_t a;
    asm("{ .reg .u64 t; cvta.to.shared.u64 t, %1; cvt.u32.u64 %0, t; }" : "=r"(a) : "l"(p));
    return a;
}
__device__ __forceinline__ uint32_t f2tf32(float f) {
    uint32_t r;
    asm("cvt.rna.tf32.f32 %0, %1;" : "=r"(r) : "f"(f));
    return r;
}
__device__ __forceinline__ void ldmx4(uint32_t* r, uint32_t addr) {
    asm volatile("ldmatrix.sync.aligned.m8n8.x4.shared.b16 {%0,%1,%2,%3}, [%4];"
                 : "=r"(r[0]), "=r"(r[1]), "=r"(r[2]), "=r"(r[3]) : "r"(addr));
}
__device__ __forceinline__ void mma_tf32(float* c, const uint32_t* a,
                                         uint32_t b0, uint32_t b1) {
    asm volatile(
        "mma.sync.aligned.m16n8k8.row.col.f32.tf32.tf32.f32 "
        "{%0,%1,%2,%3}, {%4,%5,%6,%7}, {%8,%9}, {%0,%1,%2,%3};"
        : "+f"(c[0]), "+f"(c[1]), "+f"(c[2]), "+f"(c[3])
        : "r"(a[0]), "r"(a[1]), "r"(a[2]), "r"(a[3]), "r"(b0), "r"(b1));
}

// ---------------- init ----------------
__global__ void init_kernel(const float* __restrict__ history) {
    int idx = blockIdx.x * blockDim.x + threadIdx.x;
    float* buf = g_scratch + O_BUF;
    int i = idx & 31;
    int t = (idx >> 5) & 127;
    int b = idx >> 12;
    buf[idx] = (t < THIST) ? history[(b * THIST + t) * 32 + i] : 0.0f;
}

// ---------------- tf32 GEMM: Y[128-tile,64-tile] = A[M,K] @ W[N,K]^T ----------------
// mode 0: plain fp32 out; mode 1: +bias,gelu fp32 out; mode 2: +bias fp32 out.
#define ASTRF 36                 // padded fp32 row stride (144B, ldmatrix conflict-free)
#define SM_A (128 * ASTRF)       // floats
#define SM_B (64 * ASTRF)
#define SM_BUF (SM_A + SM_B)
#define TCSMEM (2 * SM_BUF * 4)  // bytes = 55296

__device__ __forceinline__ void tf32_gemm_body(
    const float* __restrict__ A, const float* __restrict__ W,
    const float* __restrict__ bias, float* __restrict__ out,
    int N, int K, int mode, int bn, int bm, float* sm)
{
    const int tid = threadIdx.x;
    const int warp = tid >> 5, lane = tid & 31;
    const int wm = (warp & 3) * 32;     // warp row in 128
    const int wn = (warp >> 2) * 32;    // warp col in 64

    // global load indexing
    const int arow = tid >> 1;                 // 0..127
    const int acol = (tid & 1) * 16;           // 2 threads/row, 16 floats each
    const int brow = tid >> 2;                 // 0..63
    const int bcol = (tid & 3) * 8;            // 4 threads/row, 8 floats each

    const float* Ag = A + (size_t)(bm + arow) * K + acol;
    const float* Wg = W + (size_t)(bn + brow) * K + bcol;

    float acc[2][4][4];
#pragma unroll
    for (int mt = 0; mt < 2; mt++)
#pragma unroll
        for (int nt = 0; nt < 4; nt++)
#pragma unroll
            for (int i = 0; i < 4; i++) acc[mt][nt][i] = 0.0f;

    const int C = K >> 5;   // 32-wide chunks

    float4 pa[4], pb[2];
#pragma unroll
    for (int q = 0; q < 4; q++) pa[q] = *(const float4*)(Ag + q * 4);
#pragma unroll
    for (int q = 0; q < 2; q++) pb[q] = *(const float4*)(Wg + q * 4);

    // store chunk 0
    {
        float* ab = sm;
        float* bb = sm + SM_A;
        uint32_t* ap = (uint32_t*)(ab + arow * ASTRF + acol);
        uint32_t* bp = (uint32_t*)(bb + brow * ASTRF + bcol);
#pragma unroll
        for (int q = 0; q < 4; q++) {
            ap[q * 4 + 0] = f2tf32(pa[q].x); ap[q * 4 + 1] = f2tf32(pa[q].y);
            ap[q * 4 + 2] = f2tf32(pa[q].z); ap[q * 4 + 3] = f2tf32(pa[q].w);
        }
#pragma unroll
        for (int q = 0; q < 2; q++) {
            bp[q * 4 + 0] = f2tf32(pb[q].x); bp[q * 4 + 1] = f2tf32(pb[q].y);
            bp[q * 4 + 2] = f2tf32(pb[q].z); bp[q * 4 + 3] = f2tf32(pb[q].w);
        }
    }
    __syncthreads();

    const int t8 = lane & 7;
    const int amatr = ((lane >> 3) & 1) * 8;   // +8 rows for mats 1,3
    const int acolq = (lane >> 4) * 4;         // +4 cols for mats 2,3
    const int bmatn = (lane >> 4) * 8;         // +8 n for mats 2,3
    const int bcolq = ((lane >> 3) & 1) * 4;   // +4 k for mats 1,3

    for (int c = 0; c < C; c++) {
        if (c + 1 < C) {
            int k0 = (c + 1) << 5;
#pragma unroll
            for (int q = 0; q < 4; q++) pa[q] = *(const float4*)(Ag + k0 + q * 4);
#pragma unroll
            for (int q = 0; q < 2; q++) pb[q] = *(const float4*)(Wg + k0 + q * 4);
        }

        float* ab = sm + (c & 1) * SM_BUF;
        float* bb = ab + SM_A;
        uint32_t sA = smem_u32(ab);
        uint32_t sB = smem_u32(bb);

#pragma unroll
        for (int ks = 0; ks < 4; ks++) {
            int kc0 = ks * 8;
            uint32_t af[2][4];
#pragma unroll
            for (int mt = 0; mt < 2; mt++) {
                uint32_t addr = sA + ((wm + mt * 16 + t8 + amatr) * ASTRF + kc0 + acolq) * 4u;
                ldmx4(af[mt], addr);
            }
            uint32_t bf[2][4];
#pragma unroll
            for (int nh = 0; nh < 2; nh++) {
                uint32_t addr = sB + ((wn + nh * 16 + t8 + bmatn) * ASTRF + kc0 + bcolq) * 4u;
                ldmx4(bf[nh], addr);
            }
#pragma unroll
            for (int mt = 0; mt < 2; mt++) {
                mma_tf32(acc[mt][0], af[mt], bf[0][0], bf[0][1]);
                mma_tf32(acc[mt][1], af[mt], bf[0][2], bf[0][3]);
                mma_tf32(acc[mt][2], af[mt], bf[1][0], bf[1][1]);
                mma_tf32(acc[mt][3], af[mt], bf[1][2], bf[1][3]);
            }
        }

        if (c + 1 < C) {
            float* ab2 = sm + ((c + 1) & 1) * SM_BUF;
            float* bb2 = ab2 + SM_A;
            uint32_t* ap = (uint32_t*)(ab2 + arow * ASTRF + acol);
            uint32_t* bp = (uint32_t*)(bb2 + brow * ASTRF + bcol);
#pragma unroll
            for (int q = 0; q < 4; q++) {
                ap[q * 4 + 0] = f2tf32(pa[q].x); ap[q * 4 + 1] = f2tf32(pa[q].y);
                ap[q * 4 + 2] = f2tf32(pa[q].z); ap[q * 4 + 3] = f2tf32(pa[q].w);
            }
#pragma unroll
            for (int q = 0; q < 2; q++) {
                bp[q * 4 + 0] = f2tf32(pb[q].x); bp[q * 4 + 1] = f2tf32(pb[q].y);
                bp[q * 4 + 2] = f2tf32(pb[q].z); bp[q * 4 + 3] = f2tf32(pb[q].w);
            }
            __syncthreads();
        }
    }

    // epilogue: c0/c1 at (row=lane/4, col=2*(lane%4)), c2/c3 at row+8
    const int l4 = lane >> 2;
    const int l2 = (lane & 3) * 2;
#pragma unroll
    for (int mt = 0; mt < 2; mt++) {
#pragma unroll
        for (int half = 0; half < 2; half++) {
            int m = bm + wm + mt * 16 + l4 + half * 8;
            size_t rowb = (size_t)m * N;
#pragma unroll
            for (int nt = 0; nt < 4; nt++) {
                int n = bn + wn + nt * 8 + l2;
                float v0 = acc[mt][nt][half * 2 + 0];
                float v1 = acc[mt][nt][half * 2 + 1];
                if (mode >= 1) { v0 += bias[n]; v1 += bias[n + 1]; }
                if (mode == 1) { v0 = gelu_f(v0); v1 = gelu_f(v1); }
                float2 fv; fv.x = v0; fv.y = v1;
                *(float2*)(out + rowb + n) = fv;
            }
        }
    }
}

__global__ __launch_bounds__(256) void tf32_gemm_kernel(
    int aOff, const float* __restrict__ W, const float* __restrict__ bias,
    int oOff, int N, int K, int mode)
{
    extern __shared__ float sm[];
    tf32_gemm_body(g_scratch + aOff, W, bias, g_scratch + oOff,
                   N, K, mode, blockIdx.x * 64, blockIdx.y * 128, sm);
}

__global__ __launch_bounds__(256) void tf32_qkv_kernel(
    const float* __restrict__ Wq, const float* __restrict__ Wk,
    const float* __restrict__ Wv)
{
    extern __shared__ float sm[];
    const float* W = (blockIdx.z == 0) ? Wq : (blockIdx.z == 1) ? Wk : Wv;
    int oOff = O_Q + blockIdx.z * 262144;
    tf32_gemm_body(g_scratch + O_H, W, nullptr, g_scratch + oOff,
                   512, 512, 0, blockIdx.x * 64, blockIdx.y * 128, sm);
}

// ---------------- embed (fp32 SIMT, K=32) ----------------
__global__ void embed_kernel(const float* __restrict__ W, const float* __restrict__ bias) {
    __shared__ __align__(16) float Xs[16][32];
    __shared__ __align__(16) float Ws[16][64];
    const float* X = g_scratch + O_BUF;
    float* Y = g_scratch + O_H;
    int tid = threadIdx.x;
    int tx = tid & 15, ty = tid >> 4;
    int bm = blockIdx.y * 32, bn = blockIdx.x * 64;
    int lrow = tid >> 2;
    int lk4 = (tid & 3) * 4;
    const int K = 32;

    float acc[2][4];
#pragma unroll
    for (int i = 0; i < 2; i++)
#pragma unroll
        for (int j = 0; j < 4; j++) acc[i][j] = 0.0f;

    for (int k0 = 0; k0 < K; k0 += 16) {
        float4 wv = *(const float4*)(W + (size_t)(bn + lrow) * K + k0 + lk4);
        Ws[lk4 + 0][lrow] = wv.x; Ws[lk4 + 1][lrow] = wv.y;
        Ws[lk4 + 2][lrow] = wv.z; Ws[lk4 + 3][lrow] = wv.w;
        if (tid < 128) {
            float4 xv = *(const float4*)(X + (size_t)(bm + (lrow & 31)) * K + k0 + lk4);
            Xs[lk4 + 0][lrow] = xv.x; Xs[lk4 + 1][lrow] = xv.y;
            Xs[lk4 + 2][lrow] = xv.z; Xs[lk4 + 3][lrow] = xv.w;
        }
        __syncthreads();
#pragma unroll
        for (int kk = 0; kk < 16; kk++) {
            float2 xr = *(const float2*)(&Xs[kk][ty * 2]);
            float4 wr = *(const float4*)(&Ws[kk][tx * 4]);
            acc[0][0] = fmaf(xr.x, wr.x, acc[0][0]);
            acc[0][1] = fmaf(xr.x, wr.y, acc[0][1]);
            acc[0][2] = fmaf(xr.x, wr.z, acc[0][2]);
            acc[0][3] = fmaf(xr.x, wr.w, acc[0][3]);
            acc[1][0] = fmaf(xr.y, wr.x, acc[1][0]);
            acc[1][1] = fmaf(xr.y, wr.y, acc[1][1]);
            acc[1][2] = fmaf(xr.y, wr.z, acc[1][2]);
            acc[1][3] = fmaf(xr.y, wr.w, acc[1][3]);
        }
        __syncthreads();
    }

#pragma unroll
    for (int i = 0; i < 2; i++) {
        int row = bm + ty * 2 + i;
#pragma unroll
        for (int j = 0; j < 4; j++) {
            int col = bn + tx * 4 + j;
            float v = acc[i][j] + bias[col];
            int t = row & 127;
            int i2 = col >> 1;
            float freq = expf(-0.017988946038835852f * (float)(2 * i2));
            float ang = (float)t * freq;
            float pe = (col & 1) ? cosf(ang) : sinf(ang);
            Y[(size_t)row * DM + col] = v * SCALE_EMB + pe;
        }
    }
}

// ---------------- attention ----------------
__global__ void attn_kernel() {
    int qc = blockIdx.x, hh = blockIdx.y, b = blockIdx.z;
    int tid = threadIdx.x;
    int warp = tid >> 5, lane = tid & 31;

    __shared__ float Ks[64][132];
    __shared__ float Qs[32][64];
    __shared__ float Wb[8][128];

    const float* q = g_scratch + O_Q;
    const float* k = g_scratch + O_K;
    const float* v = g_scratch + O_V;
    float* out = g_scratch + O_ATTN;

    const float* kbase = k + (size_t)b * TT * DM + hh * DH;
    for (int idx = tid; idx < 128 * 16; idx += 256) {
        int kv = idx & 127, d4 = (idx >> 7) * 4;
        float4 val = *(const float4*)(kbase + (size_t)kv * DM + d4);
        Ks[d4 + 0][kv] = val.x; Ks[d4 + 1][kv] = val.y;
        Ks[d4 + 2][kv] = val.z; Ks[d4 + 3][kv] = val.w;
    }
    const float* qbase = q + ((size_t)b * TT + qc * 32) * DM + hh * DH;
    for (int idx = tid; idx < 32 * 16; idx += 256) {
        int qi = idx >> 4, d4 = (idx & 15) * 4;
        *(float4*)(&Qs[qi][d4]) = *(const float4*)(qbase + (size_t)qi * DM + d4);
    }
    __syncthreads();

    const float* vbase = v + (size_t)b * TT * DM + hh * DH;

#pragma unroll
    for (int qq = 0; qq < 4; qq++) {
        int qi = warp + qq * 8;
        int qg = qc * 32 + qi;

        float acc0 = 0.f, acc1 = 0.f, acc2 = 0.f, acc3 = 0.f;
#pragma unroll 8
        for (int d = 0; d < 64; d++) {
            float qv = Qs[qi][d];
            float4 kvv = *(const float4*)(&Ks[d][4 * lane]);
            acc0 = fmaf(qv, kvv.x, acc0);
            acc1 = fmaf(qv, kvv.y, acc1);
            acc2 = fmaf(qv, kvv.z, acc2);
            acc3 = fmaf(qv, kvv.w, acc3);
        }
        int kv0 = 4 * lane;
        acc0 = (kv0 + 0 <= qg) ? NEGF : acc0 * 0.125f;
        acc1 = (kv0 + 1 <= qg) ? NEGF : acc1 * 0.125f;
        acc2 = (kv0 + 2 <= qg) ? NEGF : acc2 * 0.125f;
        acc3 = (kv0 + 3 <= qg) ? NEGF : acc3 * 0.125f;

        float m = fmaxf(fmaxf(acc0, acc1), fmaxf(acc2, acc3));
#pragma unroll
        for (int off = 16; off; off >>= 1)
            m = fmaxf(m, __shfl_xor_sync(0xffffffffu, m, off));
        float e0 = expf(acc0 - m), e1 = expf(acc1 - m);
        float e2 = expf(acc2 - m), e3 = expf(acc3 - m);
        float s = e0 + e1 + e2 + e3;
#pragma unroll
        for (int off = 16; off; off >>= 1)
            s += __shfl_xor_sync(0xffffffffu, s, off);
        float inv = 1.0f / s;

        Wb[warp][kv0 + 0] = e0; Wb[warp][kv0 + 1] = e1;
        Wb[warp][kv0 + 2] = e2; Wb[warp][kv0 + 3] = e3;
        __syncwarp();

        float2 o = make_float2(0.f, 0.f);
        const float* vp = vbase + 2 * lane;
#pragma unroll 4
        for (int kv = 0; kv < 128; kv++) {
            float w = Wb[warp][kv];
            float2 vv = *(const float2*)(vp + (size_t)kv * DM);
            o.x = fmaf(w, vv.x, o.x);
            o.y = fmaf(w, vv.y, o.y);
        }
        o.x *= inv; o.y *= inv;
        *(float2*)(out + ((size_t)b * TT + qg) * DM + hh * DH + 2 * lane) = o;
        __syncwarp();
    }
}

// ---------------- residual + layernorm ----------------
__global__ void ln_kernel(int addoff, const float* __restrict__ g,
                          const float* __restrict__ bta) {
    int row = blockIdx.x;
    int tid = threadIdx.x;
    float* h = g_scratch + O_H;
    const float* add = g_scratch + addoff;
    size_t base = (size_t)row * DM;
    float x0 = h[base + tid] + add[base + tid];
    float x1 = h[base + tid + 256] + add[base + tid + 256];
    __shared__ float red[256];
    red[tid] = x0 + x1;
    __syncthreads();
    for (int s = 128; s > 0; s >>= 1) {
        if (tid < s) red[tid] += red[tid + s];
        __syncthreads();
    }
    float mu = red[0] * (1.0f / 512.0f);
    __syncthreads();
    float d0 = x0 - mu, d1 = x1 - mu;
    red[tid] = d0 * d0 + d1 * d1;
    __syncthreads();
    for (int s = 128; s > 0; s >>= 1) {
        if (tid < s) red[tid] += red[tid + s];
        __syncthreads();
    }
    float rstd = rsqrtf(red[0] * (1.0f / 512.0f) + 1e-5f);
    h[base + tid] = d0 * rstd * g[tid] + bta[tid];
    h[base + tid + 256] = d1 * rstd * g[tid + 256] + bta[tid + 256];
}

// ---------------- refine head ----------------
__global__ void refine_init_kernel(int step) {
    int b = blockIdx.x, tid = threadIdx.x;
    int ptr = THIST + step;
    float* cur = g_scratch + O_CUR;
    float* ctx = g_scratch + O_CTX;
    const float* buf = g_scratch + O_BUF;
    const float* h = g_scratch + O_H;
    if (tid < 32) cur[b * 32 + tid] = buf[((size_t)b * TT + ptr - 1) * 32 + tid];
    ctx[b * 512 + tid] = h[((size_t)b * TT + ptr - 1) * DM + tid];
}

__global__ void refine_hidden_kernel(const float* __restrict__ Wr1,
                                     const float* __restrict__ br1,
                                     const float* __restrict__ W_emb,
                                     const float* __restrict__ b_emb) {
    int b = blockIdx.y;
    int tid = threadIdx.x;
    int w = tid >> 5, lane = tid & 31;
    float* hidden = g_scratch + O_HID;
    const float* ctx = g_scratch + O_CTX;
    const float* cur = g_scratch + O_CUR;

    __shared__ __align__(16) float comb[1024];
    __shared__ float curs[32];
    if (tid < 32) curs[tid] = cur[b * 32 + tid];
    __syncthreads();
    for (int r = tid; r < 512; r += 256) {
        const float* we = W_emb + (size_t)r * 32;
        float s = 0.0f;
#pragma unroll
        for (int i = 0; i < 32; i++) s = fmaf(we[i], curs[i], s);
        comb[r] = (s + b_emb[r]) * SCALE_EMB;
        comb[512 + r] = ctx[b * 512 + r];
    }
    __syncthreads();

    const float4* cb = (const float4*)comb;
    float4 c[8];
#pragma unroll
    for (int jj = 0; jj < 8; jj++) c[jj] = cb[lane + 32 * jj];
    int obase = blockIdx.x * 128 + w * 16;
    for (int oo = 0; oo < 16; oo++) {
        int o = obase + oo;
        const float4* wr = (const float4*)(Wr1 + (size_t)o * 1024);
        float s = 0.0f;
#pragma unroll
        for (int jj = 0; jj < 8; jj++) {
            float4 wv = wr[lane + 32 * jj];
            s = fmaf(wv.x, c[jj].x, s);
            s = fmaf(wv.y, c[jj].y, s);
            s = fmaf(wv.z, c[jj].z, s);
            s = fmaf(wv.w, c[jj].w, s);
        }
#pragma unroll
        for (int off = 16; off; off >>= 1) s += __shfl_down_sync(0xffffffffu, s, off);
        if (lane == 0) hidden[b * 2048 + o] = gelu_f(s + br1[o]);
    }
}

__global__ void refine_delta_kernel(const float* __restrict__ Wr2,
                                    const float* __restrict__ br2,
                                    float* __restrict__ preds, int step, int last) {
    int b = blockIdx.x;
    int tid = threadIdx.x;
    int w = tid >> 5, lane = tid & 31;
    const float* hidden = g_scratch + O_HID;
    float* cur = g_scratch + O_CUR;
    float* buf = g_scratch + O_BUF;
    const float4* hv = (const float4*)(hidden + b * 2048);
    for (int oo = 0; oo < 4; oo++) {
        int o = w * 4 + oo;
        const float4* wr = (const float4*)(Wr2 + (size_t)o * 2048);
        float s = 0.0f;
#pragma unroll
        for (int jj = 0; jj < 16; jj++) {
            float4 wv = wr[lane + 32 * jj];
            float4 hx = hv[lane + 32 * jj];
            s = fmaf(wv.x, hx.x, s);
            s = fmaf(wv.y, hx.y, s);
            s = fmaf(wv.z, hx.z, s);
            s = fmaf(wv.w, hx.w, s);
        }
#pragma unroll
        for (int off = 16; off; off >>= 1) s += __shfl_down_sync(0xffffffffu, s, off);
        if (lane == 0) {
            float nv = cur[b * 32 + o] + s + br2[o];
            cur[b * 32 + o] = nv;
            if (last) {
                buf[((size_t)b * TT + THIST + step) * 32 + o] = nv;
                preds[(b * NSTEPS + step) * 32 + o] = nv;
            }
        }
    }
}

// ---------------- host orchestration ----------------
extern "C" void kernel_launch(void* const* d_in, const int* in_sizes, int n_in,
                              void* d_out, int out_size) {
    const float* history = (const float*)d_in[0];
    const float* W_emb = (const float*)d_in[2];
    const float* b_emb = (const float*)d_in[3];
    const float* Wq = (const float*)d_in[4];
    const float* Wk = (const float*)d_in[5];
    const float* Wv = (const float*)d_in[6];
    const float* Wo = (const float*)d_in[7];
    const float* ln1g = (const float*)d_in[8];
    const float* ln1b = (const float*)d_in[9];
    const float* W1 = (const float*)d_in[10];
    const float* b1 = (const float*)d_in[11];
    const float* W2 = (const float*)d_in[12];
    const float* b2 = (const float*)d_in[13];
    const float* ln2g = (const float*)d_in[14];
    const float* ln2b = (const float*)d_in[15];
    const float* Wr1 = (const float*)d_in[16];
    const float* br1 = (const float*)d_in[17];
    const float* Wr2 = (const float*)d_in[18];
    const float* br2 = (const float*)d_in[19];
    float* preds = (float*)d_out;

    static int attr_done = 0;
    if (!attr_done) {
        cudaFuncSetAttribute(tf32_gemm_kernel,
                             cudaFuncAttributeMaxDynamicSharedMemorySize, TCSMEM);
        cudaFuncSetAttribute(tf32_qkv_kernel,
                             cudaFuncAttributeMaxDynamicSharedMemorySize, TCSMEM);
        attr_done = 1;
    }

    init_kernel<<<64, 256>>>(history);

    for (int step = 0; step < NSTEPS; step++) {
        embed_kernel<<<dim3(8, 16), 256>>>(W_emb, b_emb);

        for (int l = 0; l < NL; l++) {
            tf32_qkv_kernel<<<dim3(8, 4, 3), 256, TCSMEM>>>(
                Wq + (size_t)l * 262144, Wk + (size_t)l * 262144,
                Wv + (size_t)l * 262144);
            attn_kernel<<<dim3(4, 8, 4), 256>>>();
            tf32_gemm_kernel<<<dim3(8, 4), 256, TCSMEM>>>(
                O_ATTN, Wo + (size_t)l * 262144, nullptr, O_TMP, 512, 512, 0);
            ln_kernel<<<512, 256>>>(O_TMP, ln1g + l * 512, ln1b + l * 512);
            tf32_gemm_kernel<<<dim3(32, 4), 256, TCSMEM>>>(
                O_H, W1 + (size_t)l * 1048576, b1 + l * 2048, O_FF, 2048, 512, 1);
            tf32_gemm_kernel<<<dim3(8, 4), 256, TCSMEM>>>(
                O_FF, W2 + (size_t)l * 1048576, b2 + l * 512, O_TMP, 512, 2048, 2);
            ln_kernel<<<512, 256>>>(O_TMP, ln2g + l * 512, ln2b + l * 512);
        }

        refine_init_kernel<<<4, 512>>>(step);
        for (int it = 0; it < 5; it++) {
            refine_hidden_kernel<<<dim3(16, 4), 256>>>(Wr1, br1, W_emb, b_emb);
            refine_delta_kernel<<<4, 256>>>(Wr2, br2, preds, step, it == 4);
        }
    }
}